// round 15
// baseline (speedup 1.0000x reference)
#include <cuda_runtime.h>
#include <cuda_bf16.h>
#include <math.h>
#include <stdint.h>

// ============================================================================
// CouplingLayer via mma.sync (HMMA bf16, 3-MMA split = fp32-accurate GEMM).
// tcgen05 unavailable (harness PTX targets sm_103 without 'a').
// R15: R13 pipeline (BK=64, 2-stage, interleaved prefetch) with 512 threads:
//      16 warps (4m x 4n), warp tile 32x64 -> 4 warps/SMSP, acc 64 regs.
//   x[B,128] -> (output[B,128], log_det[B]),  B=32768
// ============================================================================

#define NUM_BINS 8
#define MIN_W 0.001f
#define MIN_H 0.001f
#define MIN_D 0.001f
#define INVBN 0.9999950000374997f   // 1/sqrt(1+1e-5)

#define BM 128
#define BN 256
#define BK 64
#define NTHREADS 512
// smem row stride: 64 bf16 + 8 pad = 72 bf16 = 144B (conflict-free ldmatrix).
#define TSTRIDE 72
#define A_TILE (128 * TSTRIDE * 2)              // 18432
#define B_TILE (256 * TSTRIDE * 2)              // 36864
#define SA_HI 0
#define SA_LO (A_TILE)
#define SB_HI (2 * A_TILE)
#define SB_LO (2 * A_TILE + B_TILE)
#define STAGE_BYTES (2 * A_TILE + 2 * B_TILE)   // 110592
#define SMEM_TOTAL (2 * STAGE_BYTES)            // 221184

// ---------------------------------------------------------------------------
// Static scratch (alloc-free rule)
// ---------------------------------------------------------------------------
static __device__ __align__(1024) __nv_bfloat16 g_a1_hi[(size_t)32768*64];
static __device__ __align__(1024) __nv_bfloat16 g_a1_lo[(size_t)32768*64];
static __device__ __align__(1024) __nv_bfloat16 g_w1t_hi[(size_t)2048*64];
static __device__ __align__(1024) __nv_bfloat16 g_w1t_lo[(size_t)2048*64];
static __device__ __align__(1024) __nv_bfloat16 g_w2t_hi[(size_t)2048*2048];
static __device__ __align__(1024) __nv_bfloat16 g_w2t_lo[(size_t)2048*2048];
static __device__ __align__(1024) __nv_bfloat16 g_w3t_hi[(size_t)1536*2048];
static __device__ __align__(1024) __nv_bfloat16 g_w3t_lo[(size_t)1536*2048];
static __device__ __align__(1024) __nv_bfloat16 g_h1_hi[(size_t)32768*2048];
static __device__ __align__(1024) __nv_bfloat16 g_h1_lo[(size_t)32768*2048];
static __device__ __align__(1024) __nv_bfloat16 g_h2_hi[(size_t)32768*2048];
static __device__ __align__(1024) __nv_bfloat16 g_h2_lo[(size_t)32768*2048];
static __device__ __align__(1024) float         g_params[(size_t)32768*1536];

// ---------------------------------------------------------------------------
// helpers
// ---------------------------------------------------------------------------
__device__ __forceinline__ uint32_t smem_u32(const void* p) {
    uint32_t a;
    asm("{ .reg .u64 t; cvta.to.shared.u64 t, %1; cvt.u32.u64 %0, t; }"
        : "=r"(a) : "l"(p));
    return a;
}
__device__ __forceinline__ void cpasync16(uint32_t dst, const void* src) {
    asm volatile("cp.async.cg.shared.global [%0], [%1], 16;" :: "r"(dst), "l"(src) : "memory");
}
__device__ __forceinline__ void ldsm_x4(uint32_t& r0, uint32_t& r1, uint32_t& r2, uint32_t& r3,
                                        uint32_t addr) {
    asm volatile("ldmatrix.sync.aligned.m8n8.x4.shared.b16 {%0,%1,%2,%3}, [%4];"
                 : "=r"(r0), "=r"(r1), "=r"(r2), "=r"(r3) : "r"(addr));
}
__device__ __forceinline__ void mma_bf16(float* d, const uint32_t* a, const uint32_t* b) {
    asm volatile(
        "mma.sync.aligned.m16n8k16.row.col.f32.bf16.bf16.f32 "
        "{%0,%1,%2,%3}, {%4,%5,%6,%7}, {%8,%9}, {%0,%1,%2,%3};"
        : "+f"(d[0]), "+f"(d[1]), "+f"(d[2]), "+f"(d[3])
        : "r"(a[0]), "r"(a[1]), "r"(a[2]), "r"(a[3]), "r"(b[0]), "r"(b[1]));
}
__device__ __forceinline__ uint32_t pack2(__nv_bfloat16 a, __nv_bfloat16 b) {
    return (uint32_t)__bfloat16_as_ushort(a) | ((uint32_t)__bfloat16_as_ushort(b) << 16);
}
__device__ __forceinline__ void split2(float v, __nv_bfloat16& h, __nv_bfloat16& l) {
    h = __float2bfloat16(v);
    l = __float2bfloat16(v - __bfloat162float(h));
}

// ---------------------------------------------------------------------------
// weight transpose+split body: W[K,N] fp32 -> Thi/Tlo[N,K] bf16 (one 32x32 tile)
// ---------------------------------------------------------------------------
__device__ __forceinline__ void wsplit_tile(const float* __restrict__ W, int K, int N,
                                            __nv_bfloat16* __restrict__ Thi,
                                            __nv_bfloat16* __restrict__ Tlo,
                                            int bid, float (*t)[33]) {
    const int nbx = N / 32;
    const int nb = (bid % nbx) * 32, kb = (bid / nbx) * 32;
    const int tx = threadIdx.x & 31, ty = threadIdx.x >> 5;   // 32 x 8
#pragma unroll
    for (int i = ty; i < 32; i += 8)
        t[i][tx] = W[(size_t)(kb + i) * N + nb + tx];
    __syncthreads();
#pragma unroll
    for (int i = ty; i < 32; i += 8) {
        __nv_bfloat16 h, l; split2(t[tx][i], h, l);
        size_t o = (size_t)(nb + i) * K + kb + tx;
        Thi[o] = h; Tlo[o] = l;
    }
}

// ---------------------------------------------------------------------------
// fused split A: W1 transpose+split, then x even-column split
// ---------------------------------------------------------------------------
__global__ __launch_bounds__(256)
void fused_split_a(const float* __restrict__ x,
                   __nv_bfloat16* __restrict__ xhi, __nv_bfloat16* __restrict__ xlo, int M,
                   const float* __restrict__ W1, int K1, int N1,
                   __nv_bfloat16* __restrict__ w1hi, __nv_bfloat16* __restrict__ w1lo)
{
    __shared__ float t[32][33];
    const int wblocks = (N1 / 32) * (K1 / 32);
    if ((int)blockIdx.x < wblocks) {
        wsplit_tile(W1, K1, N1, w1hi, w1lo, blockIdx.x, t);
    } else {
        int i = ((int)blockIdx.x - wblocks) * 256 + threadIdx.x;
        if (i < M * 64) {
            int m = i >> 6, j = i & 63;
            float v = x[(size_t)m * 128 + 2 * j];
            __nv_bfloat16 h, l; split2(v, h, l);
            xhi[i] = h; xlo[i] = l;
        }
    }
}

// ---------------------------------------------------------------------------
// fused split B: W2 and W3 transpose+split
// ---------------------------------------------------------------------------
__global__ __launch_bounds__(256)
void fused_split_b(const float* __restrict__ W2, int K2, int N2,
                   __nv_bfloat16* __restrict__ w2hi, __nv_bfloat16* __restrict__ w2lo,
                   const float* __restrict__ W3, int K3, int N3,
                   __nv_bfloat16* __restrict__ w3hi, __nv_bfloat16* __restrict__ w3lo)
{
    __shared__ float t[32][33];
    const int b2 = (N2 / 32) * (K2 / 32);
    if ((int)blockIdx.x < b2)
        wsplit_tile(W2, K2, N2, w2hi, w2lo, blockIdx.x, t);
    else
        wsplit_tile(W3, K3, N3, w3hi, w3lo, blockIdx.x - b2, t);
}

// ---------------------------------------------------------------------------
// HMMA GEMM:  C[M,N] = A[M,K] @ B[N,K]^T   (A,B pre-split bf16 hi/lo)
//   acc(fp32, regs) = Ahi*Bhi + Ahi*Blo + Alo*Bhi    (3-MMA split)
// MODE 0: v = gamma*relu(v+bias)*INVBN + beta -> split to Chi/Clo bf16
// MODE 1: v = v + bias                         -> Cf fp32
// Block 512 thr = 16 warps (4m x 4n), warp tile 32x64, BK=64, 2-stage
// cp.async, prefetch interleaved across ks steps.
// ---------------------------------------------------------------------------
template <int MODE>
__global__ __launch_bounds__(NTHREADS, 1)
void hmma_gemm(const __nv_bfloat16* __restrict__ Ahi, const __nv_bfloat16* __restrict__ Alo,
               const __nv_bfloat16* __restrict__ Bhi, const __nv_bfloat16* __restrict__ Blo,
               const float* __restrict__ bias, const float* __restrict__ gamma,
               const float* __restrict__ beta,
               __nv_bfloat16* __restrict__ Chi, __nv_bfloat16* __restrict__ Clo,
               float* __restrict__ Cf, int N, int K)
{
    extern __shared__ char smem_c[];
    const uint32_t sbase = smem_u32(smem_c);
    const int tid  = threadIdx.x;
    const int wid  = tid >> 5, lane = tid & 31;
    const int wm   = wid >> 2;          // 0..3  (m band of 32)
    const int wn   = wid & 3;           // 0..3  (n band of 64)
    const long rowBlock = (long)blockIdx.y * BM;
    const int  colBlock = blockIdx.x * BN;

    float acc[2][8][4];
#pragma unroll
    for (int a = 0; a < 2; a++)
#pragma unroll
        for (int b = 0; b < 8; b++)
#pragma unroll
            for (int c = 0; c < 4; c++) acc[a][b][c] = 0.f;

    // cp.async mapping per chunk (512 threads):
    //   A: 1024 16B-chunks per array -> 2/thread;  B: 2048 -> 4/thread.
    auto issue_chunk = [&](int kc, int s) {
        const uint32_t stage = sbase + s * STAGE_BYTES;
        const long kOff = (long)kc * BK;
#pragma unroll
        for (int t = 0; t < 2; t++) {
            const int idx = tid + t * NTHREADS;
            const int r = idx >> 3, c = idx & 7;
            const uint32_t dso = r * (TSTRIDE * 2) + c * 16;
            const long aoff = (rowBlock + r) * (long)K + kOff + c * 8;
            cpasync16(stage + SA_HI + dso, Ahi + aoff);
            cpasync16(stage + SA_LO + dso, Alo + aoff);
        }
#pragma unroll
        for (int t = 0; t < 4; t++) {
            const int idx = tid + t * NTHREADS;
            const int r = idx >> 3, c = idx & 7;
            const uint32_t dso = r * (TSTRIDE * 2) + c * 16;
            const long boff = (colBlock + r) * (long)K + kOff + c * 8;
            cpasync16(stage + SB_HI + dso, Bhi + boff);
            cpasync16(stage + SB_LO + dso, Blo + boff);
        }
        asm volatile("cp.async.commit_group;" ::: "memory");
    };

    // quarter-chunk prefetch, part p in 0..3:
    //   p<2: {Ahi,Alo} slab p;  all p: {Bhi,Blo} slab p.   Total 12 ops/thread.
    auto issue_part = [&](int kc, int s, int p) {
        const uint32_t stage = sbase + s * STAGE_BYTES;
        const long kOff = (long)kc * BK;
        if (p < 2) {
            const int idx = tid + p * NTHREADS;
            const int r = idx >> 3, c = idx & 7;
            const uint32_t dso = r * (TSTRIDE * 2) + c * 16;
            const long aoff = (rowBlock + r) * (long)K + kOff + c * 8;
            cpasync16(stage + SA_HI + dso, Ahi + aoff);
            cpasync16(stage + SA_LO + dso, Alo + aoff);
        }
        {
            const int idx = tid + p * NTHREADS;
            const int r = idx >> 3, c = idx & 7;
            const uint32_t dso = r * (TSTRIDE * 2) + c * 16;
            const long boff = (colBlock + r) * (long)K + kOff + c * 8;
            cpasync16(stage + SB_HI + dso, Bhi + boff);
            cpasync16(stage + SB_LO + dso, Blo + boff);
        }
    };

    const int KT = K / BK;
    issue_chunk(0, 0);

    // ldmatrix per-lane address components
    const int a_row = wm * 32 + (lane & 15);        // + tm*16
    const int a_k8  = (lane >> 4);                  // 0/1 -> +8 k
    // B paired x4: lg = lane>>3: (pair half lg>>1, k8 = lg&1)
    const int lg     = lane >> 3;
    const int bp_row = wn * 64 + ((lg >> 1) * 8) + (lane & 7);   // + half*32 + tnp*16
    const int bp_k8  = lg & 1;

    for (int it = 0; it < KT; ++it) {
        asm volatile("cp.async.wait_group 0;" ::: "memory");
        __syncthreads();

        const bool pf = (it + 1 < KT);
        const int  s1 = (it + 1) & 1;
        const uint32_t stage = sbase + (it & 1) * STAGE_BYTES;
#pragma unroll
        for (int ks = 0; ks < 4; ks++) {       // 4 x k16 per BK=64 chunk
            uint32_t ahi[2][4], alo[2][4];
            const uint32_t a_base = stage + a_row * (TSTRIDE * 2) + ks * 32 + a_k8 * 16;
            const uint32_t b_base = stage + bp_row * (TSTRIDE * 2) + ks * 32 + bp_k8 * 16;
#pragma unroll
            for (int tm = 0; tm < 2; tm++) {
                const uint32_t ad = a_base + tm * 16 * (TSTRIDE * 2);
                ldsm_x4(ahi[tm][0], ahi[tm][1], ahi[tm][2], ahi[tm][3], SA_HI + ad);
                ldsm_x4(alo[tm][0], alo[tm][1], alo[tm][2], alo[tm][3], SA_LO + ad);
            }
#pragma unroll
            for (int half = 0; half < 2; half++) {   // 4 n-tiles per half
                uint32_t bhi[4][2], blo[4][2];
#pragma unroll
                for (int tnp = 0; tnp < 2; tnp++) {
                    const uint32_t bd = b_base + (half * 32 + tnp * 16) * (TSTRIDE * 2);
                    ldsm_x4(bhi[2*tnp][0], bhi[2*tnp][1], bhi[2*tnp+1][0], bhi[2*tnp+1][1],
                            SB_HI + bd);
                    ldsm_x4(blo[2*tnp][0], blo[2*tnp][1], blo[2*tnp+1][0], blo[2*tnp+1][1],
                            SB_LO + bd);
                }
#pragma unroll
                for (int tm = 0; tm < 2; tm++)
#pragma unroll
                    for (int tnl = 0; tnl < 4; tnl++) {
                        float* d = acc[tm][half * 4 + tnl];
                        mma_bf16(d, ahi[tm], bhi[tnl]);
                        mma_bf16(d, ahi[tm], blo[tnl]);
                        mma_bf16(d, alo[tm], bhi[tnl]);
                    }
            }
            if (pf) issue_part(it + 1, s1, ks);   // spread MIO pressure
        }
        if (pf) asm volatile("cp.async.commit_group;" ::: "memory");
        // no trailing sync: distance-2 stage reuse ordered by top-of-loop sync.
    }

    // Epilogue: fragment layout d0..d3 -> (g, qp) rows/cols
    const int g  = lane >> 2;        // 0..7
    const int qp = lane & 3;         // 0..3
#pragma unroll
    for (int tm = 0; tm < 2; tm++) {
        const long r0 = rowBlock + wm * 32 + tm * 16 + g;
        const long r1 = r0 + 8;
#pragma unroll
        for (int tn = 0; tn < 8; tn++) {
            const int c0 = colBlock + wn * 64 + tn * 8 + qp * 2;
            const float b0 = __ldg(&bias[c0]);
            const float b1 = __ldg(&bias[c0 + 1]);
            float v00 = acc[tm][tn][0] + b0;
            float v01 = acc[tm][tn][1] + b1;
            float v10 = acc[tm][tn][2] + b0;
            float v11 = acc[tm][tn][3] + b1;
            if (MODE == 0) {
                const float g0 = __ldg(&gamma[c0]),     e0 = __ldg(&beta[c0]);
                const float g1 = __ldg(&gamma[c0 + 1]), e1 = __ldg(&beta[c0 + 1]);
                v00 = fmaxf(v00, 0.f) * INVBN * g0 + e0;
                v01 = fmaxf(v01, 0.f) * INVBN * g1 + e1;
                v10 = fmaxf(v10, 0.f) * INVBN * g0 + e0;
                v11 = fmaxf(v11, 0.f) * INVBN * g1 + e1;
                __nv_bfloat16 h00, l00, h01, l01, h10, l10, h11, l11;
                split2(v00, h00, l00); split2(v01, h01, l01);
                split2(v10, h10, l10); split2(v11, h11, l11);
                *(uint32_t*)((char*)Chi + (r0 * N + c0) * 2) = pack2(h00, h01);
                *(uint32_t*)((char*)Chi + (r1 * N + c0) * 2) = pack2(h10, h11);
                *(uint32_t*)((char*)Clo + (r0 * N + c0) * 2) = pack2(l00, l01);
                *(uint32_t*)((char*)Clo + (r1 * N + c0) * 2) = pack2(l10, l11);
            } else {
                *(float2*)(Cf + r0 * N + c0) = make_float2(v00, v01);
                *(float2*)(Cf + r1 * N + c0) = make_float2(v10, v11);
            }
        }
    }
}

// ---------------------------------------------------------------------------
// RQ spline + output assembly (unchanged from passing round-13 kernel)
// ---------------------------------------------------------------------------
__global__ __launch_bounds__(256)
void spline_kernel(const float* __restrict__ x,
                   const float* __restrict__ params,
                   float* __restrict__ out,
                   float* __restrict__ ld_out)
{
    __shared__ float sp[4 * 1536];
    __shared__ float wsum[8];

    const int  tid     = threadIdx.x;
    const long rowBase = (long)blockIdx.x * 4;

    const float4* psrc = reinterpret_cast<const float4*>(params + rowBase * 1536);
    float4*       pdst = reinterpret_cast<float4*>(sp);
#pragma unroll
    for (int i = 0; i < 6; i++) pdst[tid + 256 * i] = psrc[tid + 256 * i];
    __syncthreads();

    const int  r = tid >> 6;
    const int  i = tid & 63;
    const long b = rowBase + r;

    const float2 xv2 = reinterpret_cast<const float2*>(x + b * 128)[i];
    const float  xe  = xv2.x;
    const float  xv  = xv2.y;

    const float* p = sp + r * 1536 + i * 24;

    float cw[9], ch[9], dd[9];
    {
        float mx = p[0];
#pragma unroll
        for (int j = 1; j < 8; j++) mx = fmaxf(mx, p[j]);
        float e[8]; float s = 0.f;
#pragma unroll
        for (int j = 0; j < 8; j++) { e[j] = expf(p[j] - mx); s += e[j]; }
        const float rs = (1.0f - 8.0f * MIN_W) / s;
        float c = 0.f; cw[0] = 0.f;
#pragma unroll
        for (int j = 0; j < 8; j++) { c += MIN_W + rs * e[j]; cw[j + 1] = c; }
    }
    {
        float mx = p[8];
#pragma unroll
        for (int j = 1; j < 8; j++) mx = fmaxf(mx, p[8 + j]);
        float e[8]; float s = 0.f;
#pragma unroll
        for (int j = 0; j < 8; j++) { e[j] = expf(p[8 + j] - mx); s += e[j]; }
        const float rs = (1.0f - 8.0f * MIN_H) / s;
        float c = 0.f; ch[0] = 0.f;
#pragma unroll
        for (int j = 0; j < 8; j++) { c += MIN_H + rs * e[j]; ch[j + 1] = c; }
    }
    {
#pragma unroll
        for (int j = 0; j < 8; j++) {
            const float v = p[16 + j];
            dd[j] = MIN_D + (fmaxf(v, 0.f) + log1pf(expf(-fabsf(v))));
        }
        dd[8] = MIN_D;
    }

    int c = 0;
#pragma unroll
    for (int j = 0; j < 8; j++) c += (xv > cw[j]) ? 1 : 0;
    c = min(c, 7);

    float xl = cw[0], xr = cw[1], yl = ch[0], yr = ch[1], dl = dd[0], dr = dd[1];
#pragma unroll
    for (int j = 1; j < 8; j++) {
        if (c == j) {
            xl = cw[j]; xr = cw[j + 1];
            yl = ch[j]; yr = ch[j + 1];
            dl = dd[j]; dr = dd[j + 1];
        }
    }

    const float bw  = xr - xl;
    const float bh  = yr - yl;
    float t = (xv - xl) / bw;
    t = fminf(fmaxf(t, 0.f), 1.f);
    const float omt = 1.f - t;
    const float num = bh * (dl * t * t + 2.f * t * omt);
    const float den = dl + (dr - dl) * t;
    const float tr  = yl + num / den;
    float ld = logf(bh) + 2.f * logf(2.f * t * omt * dr + dl) - logf(den);

    reinterpret_cast<float2*>(out + b * 128)[i] = make_float2(xe, tr);

#pragma unroll
    for (int off = 16; off > 0; off >>= 1)
        ld += __shfl_down_sync(0xffffffffu, ld, off);
    if ((tid & 31) == 0) wsum[tid >> 5] = ld;
    __syncthreads();
    if (tid < 4) ld_out[rowBase + tid] = wsum[2 * tid] + wsum[2 * tid + 1];
}

// ---------------------------------------------------------------------------
extern "C" void kernel_launch(void* const* d_in, const int* in_sizes, int n_in,
                              void* d_out, int out_size)
{
    const float* x   = (const float*)d_in[0];
    const float* W1  = (const float*)d_in[1];
    const float* b1  = (const float*)d_in[2];
    const float* g1  = (const float*)d_in[3];
    const float* be1 = (const float*)d_in[4];
    const float* W2  = (const float*)d_in[5];
    const float* b2  = (const float*)d_in[6];
    const float* g2  = (const float*)d_in[7];
    const float* be2 = (const float*)d_in[8];
    const float* W3  = (const float*)d_in[9];
    const float* b3  = (const float*)d_in[10];

    const int M    = in_sizes[0] / 128;   // 32768
    const int H    = in_sizes[2];         // 2048
    const int Dout = in_sizes[10];        // 1536
    const int K1   = in_sizes[1] / H;     // 64

    static bool g_init = false;
    static __nv_bfloat16 *a1hi, *a1lo, *w1hi, *w1lo, *w2hi, *w2lo, *w3hi, *w3lo;
    static __nv_bfloat16 *h1hi, *h1lo, *h2hi, *h2lo;
    static float *params;
    if (!g_init) {
        cudaGetSymbolAddress((void**)&a1hi, g_a1_hi);
        cudaGetSymbolAddress((void**)&a1lo, g_a1_lo);
        cudaGetSymbolAddress((void**)&w1hi, g_w1t_hi);
        cudaGetSymbolAddress((void**)&w1lo, g_w1t_lo);
        cudaGetSymbolAddress((void**)&w2hi, g_w2t_hi);
        cudaGetSymbolAddress((void**)&w2lo, g_w2t_lo);
        cudaGetSymbolAddress((void**)&w3hi, g_w3t_hi);
        cudaGetSymbolAddress((void**)&w3lo, g_w3t_lo);
        cudaGetSymbolAddress((void**)&h1hi, g_h1_hi);
        cudaGetSymbolAddress((void**)&h1lo, g_h1_lo);
        cudaGetSymbolAddress((void**)&h2hi, g_h2_hi);
        cudaGetSymbolAddress((void**)&h2lo, g_h2_lo);
        cudaGetSymbolAddress((void**)&params, g_params);
        cudaFuncSetAttribute(hmma_gemm<0>, cudaFuncAttributeMaxDynamicSharedMemorySize, SMEM_TOTAL);
        cudaFuncSetAttribute(hmma_gemm<1>, cudaFuncAttributeMaxDynamicSharedMemorySize, SMEM_TOTAL);
        g_init = true;
    }

    float* out  = (float*)d_out;
    float* ldet = out + (size_t)M * 128;

    // Launch order keeps ncu's captured launch (index 3) on GEMM2:
    //   0: fused_split_a  1: gemm1  2: fused_split_b  3: gemm2  4: gemm3  5: spline
    const int wblocksA = (H / 32) * (K1 / 32);                 // 128
    fused_split_a<<<wblocksA + (M * 64 + 255) / 256, 256>>>(
        x, a1hi, a1lo, M, W1, K1, H, w1hi, w1lo);

    hmma_gemm<0><<<dim3(H / BN, M / BM), NTHREADS, SMEM_TOTAL>>>(
        a1hi, a1lo, w1hi, w1lo, b1, g1, be1, h1hi, h1lo, nullptr, H, K1);

    const int b2blocks = (H / 32) * (H / 32);                  // 4096
    const int b3blocks = (Dout / 32) * (H / 32);               // 3072
    fused_split_b<<<b2blocks + b3blocks, 256>>>(
        W2, H, H, w2hi, w2lo, W3, H, Dout, w3hi, w3lo);

    hmma_gemm<0><<<dim3(H / BN, M / BM), NTHREADS, SMEM_TOTAL>>>(
        h1hi, h1lo, w2hi, w2lo, b2, g2, be2, h2hi, h2lo, nullptr, H, H);
    hmma_gemm<1><<<dim3(Dout / BN, M / BM), NTHREADS, SMEM_TOTAL>>>(
        h2hi, h2lo, w3hi, w3lo, b3, nullptr, nullptr, nullptr, nullptr, params, Dout, H);

    spline_kernel<<<M / 4, 256>>>(x, params, out, ldet);
}

// round 17
// speedup vs baseline: 1.0403x; 1.0403x over previous
#include <cuda_runtime.h>
#include <cuda_bf16.h>
#include <math.h>
#include <stdint.h>

// ============================================================================
// CouplingLayer via mma.sync (HMMA bf16, 3-MMA split = fp32-accurate GEMM).
// tcgen05 unavailable (harness PTX targets sm_103 without 'a').
// R16: R13 config (256 thr, BK=64, 2-stage, interleaved prefetch) with
//      TERM-MAJOR MMA ordering: 16 independent MMAs per split term, breaking
//      the 3-deep accumulator RAW chains of the (tm,tn)-major order.
//   x[B,128] -> (output[B,128], log_det[B]),  B=32768
// ============================================================================

#define NUM_BINS 8
#define MIN_W 0.001f
#define MIN_H 0.001f
#define MIN_D 0.001f
#define INVBN 0.9999950000374997f   // 1/sqrt(1+1e-5)

#define BM 128
#define BN 256
#define BK 64
// smem row stride: 64 bf16 + 8 pad = 72 bf16 = 144B (conflict-free ldmatrix).
#define TSTRIDE 72
#define A_TILE (128 * TSTRIDE * 2)              // 18432
#define B_TILE (256 * TSTRIDE * 2)              // 36864
#define SA_HI 0
#define SA_LO (A_TILE)
#define SB_HI (2 * A_TILE)
#define SB_LO (2 * A_TILE + B_TILE)
#define STAGE_BYTES (2 * A_TILE + 2 * B_TILE)   // 110592
#define SMEM_TOTAL (2 * STAGE_BYTES)            // 221184

// ---------------------------------------------------------------------------
// Static scratch (alloc-free rule)
// ---------------------------------------------------------------------------
static __device__ __align__(1024) __nv_bfloat16 g_a1_hi[(size_t)32768*64];
static __device__ __align__(1024) __nv_bfloat16 g_a1_lo[(size_t)32768*64];
static __device__ __align__(1024) __nv_bfloat16 g_w1t_hi[(size_t)2048*64];
static __device__ __align__(1024) __nv_bfloat16 g_w1t_lo[(size_t)2048*64];
static __device__ __align__(1024) __nv_bfloat16 g_w2t_hi[(size_t)2048*2048];
static __device__ __align__(1024) __nv_bfloat16 g_w2t_lo[(size_t)2048*2048];
static __device__ __align__(1024) __nv_bfloat16 g_w3t_hi[(size_t)1536*2048];
static __device__ __align__(1024) __nv_bfloat16 g_w3t_lo[(size_t)1536*2048];
static __device__ __align__(1024) __nv_bfloat16 g_h1_hi[(size_t)32768*2048];
static __device__ __align__(1024) __nv_bfloat16 g_h1_lo[(size_t)32768*2048];
static __device__ __align__(1024) __nv_bfloat16 g_h2_hi[(size_t)32768*2048];
static __device__ __align__(1024) __nv_bfloat16 g_h2_lo[(size_t)32768*2048];
static __device__ __align__(1024) float         g_params[(size_t)32768*1536];

// ---------------------------------------------------------------------------
// helpers
// ---------------------------------------------------------------------------
__device__ __forceinline__ uint32_t smem_u32(const void* p) {
    uint32_t a;
    asm("{ .reg .u64 t; cvta.to.shared.u64 t, %1; cvt.u32.u64 %0, t; }"
        : "=r"(a) : "l"(p));
    return a;
}
__device__ __forceinline__ void cpasync16(uint32_t dst, const void* src) {
    asm volatile("cp.async.cg.shared.global [%0], [%1], 16;" :: "r"(dst), "l"(src) : "memory");
}
__device__ __forceinline__ void ldsm_x4(uint32_t& r0, uint32_t& r1, uint32_t& r2, uint32_t& r3,
                                        uint32_t addr) {
    asm volatile("ldmatrix.sync.aligned.m8n8.x4.shared.b16 {%0,%1,%2,%3}, [%4];"
                 : "=r"(r0), "=r"(r1), "=r"(r2), "=r"(r3) : "r"(addr));
}
__device__ __forceinline__ void mma_bf16(float* d, const uint32_t* a, const uint32_t* b) {
    asm volatile(
        "mma.sync.aligned.m16n8k16.row.col.f32.bf16.bf16.f32 "
        "{%0,%1,%2,%3}, {%4,%5,%6,%7}, {%8,%9}, {%0,%1,%2,%3};"
        : "+f"(d[0]), "+f"(d[1]), "+f"(d[2]), "+f"(d[3])
        : "r"(a[0]), "r"(a[1]), "r"(a[2]), "r"(a[3]), "r"(b[0]), "r"(b[1]));
}
__device__ __forceinline__ uint32_t pack2(__nv_bfloat16 a, __nv_bfloat16 b) {
    return (uint32_t)__bfloat16_as_ushort(a) | ((uint32_t)__bfloat16_as_ushort(b) << 16);
}
__device__ __forceinline__ void split2(float v, __nv_bfloat16& h, __nv_bfloat16& l) {
    h = __float2bfloat16(v);
    l = __float2bfloat16(v - __bfloat162float(h));
}

// ---------------------------------------------------------------------------
// weight transpose+split body: W[K,N] fp32 -> Thi/Tlo[N,K] bf16 (one 32x32 tile)
// ---------------------------------------------------------------------------
__device__ __forceinline__ void wsplit_tile(const float* __restrict__ W, int K, int N,
                                            __nv_bfloat16* __restrict__ Thi,
                                            __nv_bfloat16* __restrict__ Tlo,
                                            int bid, float (*t)[33]) {
    const int nbx = N / 32;
    const int nb = (bid % nbx) * 32, kb = (bid / nbx) * 32;
    const int tx = threadIdx.x & 31, ty = threadIdx.x >> 5;   // 32 x 8
#pragma unroll
    for (int i = ty; i < 32; i += 8)
        t[i][tx] = W[(size_t)(kb + i) * N + nb + tx];
    __syncthreads();
#pragma unroll
    for (int i = ty; i < 32; i += 8) {
        __nv_bfloat16 h, l; split2(t[tx][i], h, l);
        size_t o = (size_t)(nb + i) * K + kb + tx;
        Thi[o] = h; Tlo[o] = l;
    }
}

// ---------------------------------------------------------------------------
// fused split A: W1 transpose+split, then x even-column split
// ---------------------------------------------------------------------------
__global__ __launch_bounds__(256)
void fused_split_a(const float* __restrict__ x,
                   __nv_bfloat16* __restrict__ xhi, __nv_bfloat16* __restrict__ xlo, int M,
                   const float* __restrict__ W1, int K1, int N1,
                   __nv_bfloat16* __restrict__ w1hi, __nv_bfloat16* __restrict__ w1lo)
{
    __shared__ float t[32][33];
    const int wblocks = (N1 / 32) * (K1 / 32);
    if ((int)blockIdx.x < wblocks) {
        wsplit_tile(W1, K1, N1, w1hi, w1lo, blockIdx.x, t);
    } else {
        int i = ((int)blockIdx.x - wblocks) * 256 + threadIdx.x;
        if (i < M * 64) {
            int m = i >> 6, j = i & 63;
            float v = x[(size_t)m * 128 + 2 * j];
            __nv_bfloat16 h, l; split2(v, h, l);
            xhi[i] = h; xlo[i] = l;
        }
    }
}

// ---------------------------------------------------------------------------
// fused split B: W2 and W3 transpose+split
// ---------------------------------------------------------------------------
__global__ __launch_bounds__(256)
void fused_split_b(const float* __restrict__ W2, int K2, int N2,
                   __nv_bfloat16* __restrict__ w2hi, __nv_bfloat16* __restrict__ w2lo,
                   const float* __restrict__ W3, int K3, int N3,
                   __nv_bfloat16* __restrict__ w3hi, __nv_bfloat16* __restrict__ w3lo)
{
    __shared__ float t[32][33];
    const int b2 = (N2 / 32) * (K2 / 32);
    if ((int)blockIdx.x < b2)
        wsplit_tile(W2, K2, N2, w2hi, w2lo, blockIdx.x, t);
    else
        wsplit_tile(W3, K3, N3, w3hi, w3lo, blockIdx.x - b2, t);
}

// ---------------------------------------------------------------------------
// HMMA GEMM:  C[M,N] = A[M,K] @ B[N,K]^T   (A,B pre-split bf16 hi/lo)
//   acc(fp32, regs) = Ahi*Bhi + Ahi*Blo + Alo*Bhi    (3-MMA split)
// MODE 0: v = gamma*relu(v+bias)*INVBN + beta -> split to Chi/Clo bf16
// MODE 1: v = v + bias                         -> Cf fp32
// Block 256 thr = 8 warps (2m x 4n), warp tile 64x64, BK=64, 2-stage
// cp.async, interleaved prefetch, TERM-MAJOR MMA issue (16 independent
// MMAs per term -> accumulator revisit distance 16, not 1).
// ---------------------------------------------------------------------------
template <int MODE>
__global__ __launch_bounds__(256, 1)
void hmma_gemm(const __nv_bfloat16* __restrict__ Ahi, const __nv_bfloat16* __restrict__ Alo,
               const __nv_bfloat16* __restrict__ Bhi, const __nv_bfloat16* __restrict__ Blo,
               const float* __restrict__ bias, const float* __restrict__ gamma,
               const float* __restrict__ beta,
               __nv_bfloat16* __restrict__ Chi, __nv_bfloat16* __restrict__ Clo,
               float* __restrict__ Cf, int N, int K)
{
    extern __shared__ char smem_c[];
    const uint32_t sbase = smem_u32(smem_c);
    const int tid  = threadIdx.x;
    const int wid  = tid >> 5, lane = tid & 31;
    const int wm   = wid >> 2;          // 0..1  (m band of 64)
    const int wn   = wid & 3;           // 0..3  (n band of 64)
    const long rowBlock = (long)blockIdx.y * BM;
    const int  colBlock = blockIdx.x * BN;

    float acc[4][8][4];
#pragma unroll
    for (int a = 0; a < 4; a++)
#pragma unroll
        for (int b = 0; b < 8; b++)
#pragma unroll
            for (int c = 0; c < 4; c++) acc[a][b][c] = 0.f;

    // full-chunk load (preamble only)
    auto issue_chunk = [&](int kc, int s) {
        const uint32_t stage = sbase + s * STAGE_BYTES;
        const long kOff = (long)kc * BK;
#pragma unroll
        for (int t = 0; t < 4; t++) {
            const int idx = tid + t * 256;
            const int r = idx >> 3, c = idx & 7;
            const uint32_t dso = r * (TSTRIDE * 2) + c * 16;
            const long aoff = (rowBlock + r) * (long)K + kOff + c * 8;
            cpasync16(stage + SA_HI + dso, Ahi + aoff);
            cpasync16(stage + SA_LO + dso, Alo + aoff);
        }
#pragma unroll
        for (int t = 0; t < 8; t++) {
            const int idx = tid + t * 256;
            const int r = idx >> 3, c = idx & 7;
            const uint32_t dso = r * (TSTRIDE * 2) + c * 16;
            const long boff = (colBlock + r) * (long)K + kOff + c * 8;
            cpasync16(stage + SB_HI + dso, Bhi + boff);
            cpasync16(stage + SB_LO + dso, Blo + boff);
        }
        asm volatile("cp.async.commit_group;" ::: "memory");
    };

    // quarter-chunk load: part p issues A t=p and B t={2p,2p+1} (6 ops/thread)
    auto issue_part = [&](int kc, int s, int part) {
        const uint32_t stage = sbase + s * STAGE_BYTES;
        const long kOff = (long)kc * BK;
        {
            const int idx = tid + part * 256;
            const int r = idx >> 3, c = idx & 7;
            const uint32_t dso = r * (TSTRIDE * 2) + c * 16;
            const long aoff = (rowBlock + r) * (long)K + kOff + c * 8;
            cpasync16(stage + SA_HI + dso, Ahi + aoff);
            cpasync16(stage + SA_LO + dso, Alo + aoff);
        }
#pragma unroll
        for (int u = 0; u < 2; u++) {
            const int idx = tid + (part * 2 + u) * 256;
            const int r = idx >> 3, c = idx & 7;
            const uint32_t dso = r * (TSTRIDE * 2) + c * 16;
            const long boff = (colBlock + r) * (long)K + kOff + c * 8;
            cpasync16(stage + SB_HI + dso, Bhi + boff);
            cpasync16(stage + SB_LO + dso, Blo + boff);
        }
    };

    const int KT = K / BK;
    issue_chunk(0, 0);

    // ldmatrix per-lane address components
    const int a_row = wm * 64 + (lane & 15);        // + tm*16
    const int a_k8  = (lane >> 4);                  // 0/1 -> +8 k
    // B paired x4: lg = lane>>3: (pair half lg>>1, k8 = lg&1)
    const int lg     = lane >> 3;
    const int bp_row = wn * 64 + ((lg >> 1) * 8) + (lane & 7);   // + half*32 + tnp*16
    const int bp_k8  = lg & 1;

    for (int it = 0; it < KT; ++it) {
        asm volatile("cp.async.wait_group 0;" ::: "memory");
        __syncthreads();

        const bool pf = (it + 1 < KT);
        const int  s1 = (it + 1) & 1;
        const uint32_t stage = sbase + (it & 1) * STAGE_BYTES;
#pragma unroll
        for (int ks = 0; ks < 4; ks++) {       // 4 x k16 per BK=64 chunk
            uint32_t ahi[4][4], alo[4][4];
            const uint32_t a_base = stage + a_row * (TSTRIDE * 2) + ks * 32 + a_k8 * 16;
            const uint32_t b_base = stage + bp_row * (TSTRIDE * 2) + ks * 32 + bp_k8 * 16;
#pragma unroll
            for (int tm = 0; tm < 4; tm++) {
                const uint32_t ad = a_base + tm * 16 * (TSTRIDE * 2);
                ldsm_x4(ahi[tm][0], ahi[tm][1], ahi[tm][2], ahi[tm][3], SA_HI + ad);
                ldsm_x4(alo[tm][0], alo[tm][1], alo[tm][2], alo[tm][3], SA_LO + ad);
            }
#pragma unroll
            for (int half = 0; half < 2; half++) {   // 4 n-tiles per half
                uint32_t bhi[4][2], blo[4][2];
#pragma unroll
                for (int tnp = 0; tnp < 2; tnp++) {
                    const uint32_t bd = b_base + (half * 32 + tnp * 16) * (TSTRIDE * 2);
                    ldsm_x4(bhi[2*tnp][0], bhi[2*tnp][1], bhi[2*tnp+1][0], bhi[2*tnp+1][1],
                            SB_HI + bd);
                    ldsm_x4(blo[2*tnp][0], blo[2*tnp][1], blo[2*tnp+1][0], blo[2*tnp+1][1],
                            SB_LO + bd);
                }
                // TERM-MAJOR: 16 independent MMAs per term. Per-element
                // accumulation order (hihi, hilo, lohi) is unchanged ->
                // bit-identical result; only inter-element issue order moves.
#pragma unroll
                for (int tm = 0; tm < 4; tm++)
#pragma unroll
                    for (int tnl = 0; tnl < 4; tnl++)
                        mma_bf16(acc[tm][half * 4 + tnl], ahi[tm], bhi[tnl]);
#pragma unroll
                for (int tm = 0; tm < 4; tm++)
#pragma unroll
                    for (int tnl = 0; tnl < 4; tnl++)
                        mma_bf16(acc[tm][half * 4 + tnl], ahi[tm], blo[tnl]);
#pragma unroll
                for (int tm = 0; tm < 4; tm++)
#pragma unroll
                    for (int tnl = 0; tnl < 4; tnl++)
                        mma_bf16(acc[tm][half * 4 + tnl], alo[tm], bhi[tnl]);
            }
            if (pf) issue_part(it + 1, s1, ks);   // spread MIO pressure
        }
        if (pf) asm volatile("cp.async.commit_group;" ::: "memory");
        // no trailing sync: distance-2 stage reuse ordered by top-of-loop sync.
    }

    // Epilogue: fragment layout d0..d3 -> (g, qp) rows/cols
    const int g  = lane >> 2;        // 0..7
    const int qp = lane & 3;         // 0..3
#pragma unroll
    for (int tm = 0; tm < 4; tm++) {
        const long r0 = rowBlock + wm * 64 + tm * 16 + g;
        const long r1 = r0 + 8;
#pragma unroll
        for (int tn = 0; tn < 8; tn++) {
            const int c0 = colBlock + wn * 64 + tn * 8 + qp * 2;
            const float b0 = __ldg(&bias[c0]);
            const float b1 = __ldg(&bias[c0 + 1]);
            float v00 = acc[tm][tn][0] + b0;
            float v01 = acc[tm][tn][1] + b1;
            float v10 = acc[tm][tn][2] + b0;
            float v11 = acc[tm][tn][3] + b1;
            if (MODE == 0) {
                const float g0 = __ldg(&gamma[c0]),     e0 = __ldg(&beta[c0]);
                const float g1 = __ldg(&gamma[c0 + 1]), e1 = __ldg(&beta[c0 + 1]);
                v00 = fmaxf(v00, 0.f) * INVBN * g0 + e0;
                v01 = fmaxf(v01, 0.f) * INVBN * g1 + e1;
                v10 = fmaxf(v10, 0.f) * INVBN * g0 + e0;
                v11 = fmaxf(v11, 0.f) * INVBN * g1 + e1;
                __nv_bfloat16 h00, l00, h01, l01, h10, l10, h11, l11;
                split2(v00, h00, l00); split2(v01, h01, l01);
                split2(v10, h10, l10); split2(v11, h11, l11);
                *(uint32_t*)((char*)Chi + (r0 * N + c0) * 2) = pack2(h00, h01);
                *(uint32_t*)((char*)Chi + (r1 * N + c0) * 2) = pack2(h10, h11);
                *(uint32_t*)((char*)Clo + (r0 * N + c0) * 2) = pack2(l00, l01);
                *(uint32_t*)((char*)Clo + (r1 * N + c0) * 2) = pack2(l10, l11);
            } else {
                *(float2*)(Cf + r0 * N + c0) = make_float2(v00, v01);
                *(float2*)(Cf + r1 * N + c0) = make_float2(v10, v11);
            }
        }
    }
}

// ---------------------------------------------------------------------------
// RQ spline + output assembly (unchanged from passing round-13 kernel)
// ---------------------------------------------------------------------------
__global__ __launch_bounds__(256)
void spline_kernel(const float* __restrict__ x,
                   const float* __restrict__ params,
                   float* __restrict__ out,
                   float* __restrict__ ld_out)
{
    __shared__ float sp[4 * 1536];
    __shared__ float wsum[8];

    const int  tid     = threadIdx.x;
    const long rowBase = (long)blockIdx.x * 4;

    const float4* psrc = reinterpret_cast<const float4*>(params + rowBase * 1536);
    float4*       pdst = reinterpret_cast<float4*>(sp);
#pragma unroll
    for (int i = 0; i < 6; i++) pdst[tid + 256 * i] = psrc[tid + 256 * i];
    __syncthreads();

    const int  r = tid >> 6;
    const int  i = tid & 63;
    const long b = rowBase + r;

    const float2 xv2 = reinterpret_cast<const float2*>(x + b * 128)[i];
    const float  xe  = xv2.x;
    const float  xv  = xv2.y;

    const float* p = sp + r * 1536 + i * 24;

    float cw[9], ch[9], dd[9];
    {
        float mx = p[0];
#pragma unroll
        for (int j = 1; j < 8; j++) mx = fmaxf(mx, p[j]);
        float e[8]; float s = 0.f;
#pragma unroll
        for (int j = 0; j < 8; j++) { e[j] = expf(p[j] - mx); s += e[j]; }
        const float rs = (1.0f - 8.0f * MIN_W) / s;
        float c = 0.f; cw[0] = 0.f;
#pragma unroll
        for (int j = 0; j < 8; j++) { c += MIN_W + rs * e[j]; cw[j + 1] = c; }
    }
    {
        float mx = p[8];
#pragma unroll
        for (int j = 1; j < 8; j++) mx = fmaxf(mx, p[8 + j]);
        float e[8]; float s = 0.f;
#pragma unroll
        for (int j = 0; j < 8; j++) { e[j] = expf(p[8 + j] - mx); s += e[j]; }
        const float rs = (1.0f - 8.0f * MIN_H) / s;
        float c = 0.f; ch[0] = 0.f;
#pragma unroll
        for (int j = 0; j < 8; j++) { c += MIN_H + rs * e[j]; ch[j + 1] = c; }
    }
    {
#pragma unroll
        for (int j = 0; j < 8; j++) {
            const float v = p[16 + j];
            dd[j] = MIN_D + (fmaxf(v, 0.f) + log1pf(expf(-fabsf(v))));
        }
        dd[8] = MIN_D;
    }

    int c = 0;
#pragma unroll
    for (int j = 0; j < 8; j++) c += (xv > cw[j]) ? 1 : 0;
    c = min(c, 7);

    float xl = cw[0], xr = cw[1], yl = ch[0], yr = ch[1], dl = dd[0], dr = dd[1];
#pragma unroll
    for (int j = 1; j < 8; j++) {
        if (c == j) {
            xl = cw[j]; xr = cw[j + 1];
            yl = ch[j]; yr = ch[j + 1];
            dl = dd[j]; dr = dd[j + 1];
        }
    }

    const float bw  = xr - xl;
    const float bh  = yr - yl;
    float t = (xv - xl) / bw;
    t = fminf(fmaxf(t, 0.f), 1.f);
    const float omt = 1.f - t;
    const float num = bh * (dl * t * t + 2.f * t * omt);
    const float den = dl + (dr - dl) * t;
    const float tr  = yl + num / den;
    float ld = logf(bh) + 2.f * logf(2.f * t * omt * dr + dl) - logf(den);

    reinterpret_cast<float2*>(out + b * 128)[i] = make_float2(xe, tr);

#pragma unroll
    for (int off = 16; off > 0; off >>= 1)
        ld += __shfl_down_sync(0xffffffffu, ld, off);
    if ((tid & 31) == 0) wsum[tid >> 5] = ld;
    __syncthreads();
    if (tid < 4) ld_out[rowBase + tid] = wsum[2 * tid] + wsum[2 * tid + 1];
}

// ---------------------------------------------------------------------------
extern "C" void kernel_launch(void* const* d_in, const int* in_sizes, int n_in,
                              void* d_out, int out_size)
{
    const float* x   = (const float*)d_in[0];
    const float* W1  = (const float*)d_in[1];
    const float* b1  = (const float*)d_in[2];
    const float* g1  = (const float*)d_in[3];
    const float* be1 = (const float*)d_in[4];
    const float* W2  = (const float*)d_in[5];
    const float* b2  = (const float*)d_in[6];
    const float* g2  = (const float*)d_in[7];
    const float* be2 = (const float*)d_in[8];
    const float* W3  = (const float*)d_in[9];
    const float* b3  = (const float*)d_in[10];

    const int M    = in_sizes[0] / 128;   // 32768
    const int H    = in_sizes[2];         // 2048
    const int Dout = in_sizes[10];        // 1536
    const int K1   = in_sizes[1] / H;     // 64

    static bool g_init = false;
    static __nv_bfloat16 *a1hi, *a1lo, *w1hi, *w1lo, *w2hi, *w2lo, *w3hi, *w3lo;
    static __nv_bfloat16 *h1hi, *h1lo, *h2hi, *h2lo;
    static float *params;
    if (!g_init) {
        cudaGetSymbolAddress((void**)&a1hi, g_a1_hi);
        cudaGetSymbolAddress((void**)&a1lo, g_a1_lo);
        cudaGetSymbolAddress((void**)&w1hi, g_w1t_hi);
        cudaGetSymbolAddress((void**)&w1lo, g_w1t_lo);
        cudaGetSymbolAddress((void**)&w2hi, g_w2t_hi);
        cudaGetSymbolAddress((void**)&w2lo, g_w2t_lo);
        cudaGetSymbolAddress((void**)&w3hi, g_w3t_hi);
        cudaGetSymbolAddress((void**)&w3lo, g_w3t_lo);
        cudaGetSymbolAddress((void**)&h1hi, g_h1_hi);
        cudaGetSymbolAddress((void**)&h1lo, g_h1_lo);
        cudaGetSymbolAddress((void**)&h2hi, g_h2_hi);
        cudaGetSymbolAddress((void**)&h2lo, g_h2_lo);
        cudaGetSymbolAddress((void**)&params, g_params);
        cudaFuncSetAttribute(hmma_gemm<0>, cudaFuncAttributeMaxDynamicSharedMemorySize, SMEM_TOTAL);
        cudaFuncSetAttribute(hmma_gemm<1>, cudaFuncAttributeMaxDynamicSharedMemorySize, SMEM_TOTAL);
        g_init = true;
    }

    float* out  = (float*)d_out;
    float* ldet = out + (size_t)M * 128;

    // Launch order keeps ncu's captured launch (index 3) on GEMM2:
    //   0: fused_split_a  1: gemm1  2: fused_split_b  3: gemm2  4: gemm3  5: spline
    const int wblocksA = (H / 32) * (K1 / 32);                 // 128
    fused_split_a<<<wblocksA + (M * 64 + 255) / 256, 256>>>(
        x, a1hi, a1lo, M, W1, K1, H, w1hi, w1lo);

    hmma_gemm<0><<<dim3(H / BN, M / BM), 256, SMEM_TOTAL>>>(
        a1hi, a1lo, w1hi, w1lo, b1, g1, be1, h1hi, h1lo, nullptr, H, K1);

    const int b2blocks = (H / 32) * (H / 32);                  // 4096
    const int b3blocks = (Dout / 32) * (H / 32);               // 3072
    fused_split_b<<<b2blocks + b3blocks, 256>>>(
        W2, H, H, w2hi, w2lo, W3, H, Dout, w3hi, w3lo);

    hmma_gemm<0><<<dim3(H / BN, M / BM), 256, SMEM_TOTAL>>>(
        h1hi, h1lo, w2hi, w2lo, b2, g2, be2, h2hi, h2lo, nullptr, H, H);
    hmma_gemm<1><<<dim3(Dout / BN, M / BM), 256, SMEM_TOTAL>>>(
        h2hi, h2lo, w3hi, w3lo, b3, nullptr, nullptr, nullptr, nullptr, params, Dout, H);

    spline_kernel<<<M / 4, 256>>>(x, params, out, ldet);
}